// round 16
// baseline (speedup 1.0000x reference)
#include <cuda_runtime.h>
#include <cuda_fp16.h>
#include <cstdint>

// Problem constants
#define NQ      8192
#define CDIM    512
#define MROWS   32768
#define TOPK    5
#define NCH     16
#define MCHUNK  (MROWS/NCH)   // 2048
#define NCAND   (NCH*TOPK)    // 80
#define RT      16            // candidates exactly rescored per query

// GEMM tiling (R13/R15 config — measured optimum of the legacy mma path)
#define THREADS   1024
#define QT        128         // queries per block
#define NT        128         // memory rows per tile
#define MT_PER    (MCHUNK/NT) // 16 tiles per block
#define KC        128         // k elements (fp8) per staged chunk
#define NKC       (CDIM/KC)   // 4
#define NCHUNKS   (MT_PER*NKC)// 64
#define NSTAGE    6           // deep cp.async ring (5-chunk prefetch distance)
#define CAP       12          // per-row bucket capacity per tile

#define SQ_STRIDE 528                          // bytes per sQ row (512 + 16 pad)
#define SM_STRIDE 144                          // bytes per sM row (128 + 16 pad)
#define SS_STRIDEH 132                         // f16 elems per sSim row (128 + 4)

#define SQ_BYTES    (QT*SQ_STRIDE)             // 67584
#define CHUNK_BYTES (NT*SM_STRIDE)             // 18432
#define SM_OFF      SQ_BYTES
#define SS_OFF      (SM_OFF + NSTAGE*CHUNK_BYTES)   // 178176
#define TH_OFF      (SS_OFF + QT*SS_STRIDEH*2)      // 211968
#define CNT_OFF     (TH_OFF + 512)                  // 212480
#define BS_OFF      (CNT_OFF + 512)                 // 212992
#define BC_OFF      (BS_OFF + QT*CAP*4)             // 219136
#define OVR_OFF     (BC_OFF + QT*CAP*4)             // 225280
#define SMEM_BYTES  (OVR_OFF + 16)                  // 225296 (< 227 KB)

// Scratch (device globals: allocation-free)
__device__ __align__(256) uint8_t g_qn8[(size_t)NQ*CDIM];     // e4m3 normalized queries
__device__ __align__(256) uint8_t g_mn8[(size_t)MROWS*CDIM];  // e4m3 normalized memory
__device__ float g_minv[MROWS];
__device__ float g_cscore[(size_t)NQ*NCAND];                  // fp8-approx scores
__device__ int   g_cidx[(size_t)NQ*NCAND];

__device__ __forceinline__ uint32_t smem_u32(const void* p){
    return (uint32_t)__cvta_generic_to_shared(p);
}
__device__ __forceinline__ float warp_sum(float v){
    #pragma unroll
    for (int o=16;o;o>>=1) v += __shfl_xor_sync(0xffffffffu, v, o);
    return v;
}
__device__ __forceinline__ void cp_async16(uint32_t dst, const void* src){
    asm volatile("cp.async.cg.shared.global [%0], [%1], 16;"
                 :: "r"(dst), "l"(src) : "memory");
}
__device__ __forceinline__ void cp_commit(){
    asm volatile("cp.async.commit_group;" ::: "memory");
}
template<int N>
__device__ __forceinline__ void cp_wait(){
    asm volatile("cp.async.wait_group %0;" :: "n"(N) : "memory");
}
// pack 2 floats -> e4m3x2 (a -> upper byte, b -> lower byte)
__device__ __forceinline__ uint16_t f2_e4m3x2(float a, float b){
    uint16_t r;
    asm("cvt.rn.satfinite.e4m3x2.f32 %0, %1, %2;" : "=h"(r) : "f"(a), "f"(b));
    return r;
}

// top-5 insert (strict >, earlier insertion wins ties)
#define TOP5_INSERT(v, id) do { \
    if ((v) > s4){ \
        if ((v) > s2){ \
            if ((v) > s1){ \
                if ((v) > s0){ s4=s3;i4=i3; s3=s2;i3=i2; s2=s1;i2=i1; s1=s0;i1=i0; s0=(v);i0=(id); } \
                else         { s4=s3;i4=i3; s3=s2;i3=i2; s2=s1;i2=i1; s1=(v);i1=(id); } \
            } else           { s4=s3;i4=i3; s3=s2;i3=i2; s2=(v);i2=(id); } \
        } else { \
            if ((v) > s3)    { s4=s3;i4=i3; s3=(v);i3=(id); } \
            else             { s4=(v);i4=(id); } \
        } \
    } \
} while(0)

// ---------------------------------------------------------------------------
// Kernel 1 (fused): L2-normalize all rows (fp32 in -> e4m3 out).
// Rows [0, NQ) are queries; rows [NQ, NQ+MROWS) are memory rows.
// ---------------------------------------------------------------------------
__global__ void normalize_all(const float* __restrict__ xg,
                              const float* __restrict__ mg){
    int row  = blockIdx.x*8 + (threadIdx.x >> 5);
    int lane = threadIdx.x & 31;
    const bool ismem = (row >= NQ);
    const int r = ismem ? (row - NQ) : row;
    if (ismem && r >= MROWS) return;
    const float* in = ismem ? mg : xg;
    uint8_t* outb = ismem ? g_mn8 : g_qn8;

    const float4* src = (const float4*)(in + (size_t)r*CDIM);
    float4 v[4];
    float ss = 0.f;
    #pragma unroll
    for (int w=0; w<4; w++){
        v[w] = src[lane + w*32];
        ss += v[w].x*v[w].x + v[w].y*v[w].y + v[w].z*v[w].z + v[w].w*v[w].w;
    }
    ss = warp_sum(ss);
    float inv = 1.0f / fmaxf(sqrtf(ss), 1e-12f);
    uint8_t* dst = outb + (size_t)r*CDIM;
    #pragma unroll
    for (int w=0; w<4; w++){
        uint32_t lo = f2_e4m3x2(v[w].y*inv, v[w].x*inv);   // bytes [x,y]
        uint32_t hi = f2_e4m3x2(v[w].w*inv, v[w].z*inv);   // bytes [z,w]
        *(uint32_t*)(dst + (lane + w*32)*4) = lo | (hi << 16);
    }
    if (ismem && lane==0) g_minv[r] = inv;
}

// ---------------------------------------------------------------------------
// Kernel 3: e4m3 mma.sync GEMM (6-stage cp.async ring; f16 selection spill).
// 1024 threads, 32 warps, warp tile 16q x 32n. Threshold-filtered top-5.
// Emits per-chunk top-5 indices AND fp8-approx scores.
// grid = (NCH=16, NQ/128=64) = 1024 blocks.
// ---------------------------------------------------------------------------
__global__ void __launch_bounds__(THREADS,1) sim_topk_fp8(){
    extern __shared__ __align__(16) char sm[];
    uint8_t* sQ      = (uint8_t*)sm;
    __half*  sSim    = (__half*)(sm + SS_OFF);
    float*   sThresh = (float*)(sm + TH_OFF);
    int*     sCnt    = (int*)(sm + CNT_OFF);
    float*   sBS     = (float*)(sm + BS_OFF);
    int*     sBC     = (int*)(sm + BC_OFF);
    int*     sOver   = (int*)(sm + OVR_OFF);

    const int tid  = threadIdx.x;
    const int lane = tid & 31;
    const int wid  = tid >> 5;
    const int chunk = blockIdx.x;
    const int qbase = blockIdx.y * QT;
    const int mbase = chunk * MCHUNK;

    if (tid == 0) sOver[0] = 0;

    // ---- Load resident Q tile (128 x 512 fp8, padded rows) ----
    {
        const uint4* gq = (const uint4*)g_qn8;   // 32 uint4 per row
        #pragma unroll
        for (int i=0; i<(QT*32)/THREADS; i++){
            int idx = tid + i*THREADS;
            int r = idx >> 5, c = idx & 31;
            uint4 v = gq[(size_t)(qbase + r)*32 + c];
            *(uint4*)(sQ + r*SQ_STRIDE + c*16) = v;
        }
    }

    // ---- producer: each thread copies 1x16B per 128x128 fp8 chunk ----
    const int rowt = tid >> 3;          // 0..127
    const int c16  = tid & 7;           // 16B column (8 per row)
    const uint8_t* gmb = g_mn8;

    auto issue_chunk = [&](int cidx){
        int mt = cidx >> 2, kc = cidx & 3;
        const uint8_t* src = gmb
            + (size_t)(mbase + mt*NT + rowt)*CDIM + kc*KC + c16*16;
        uint32_t dst = smem_u32(sm + SM_OFF
                                + (cidx % NSTAGE)*CHUNK_BYTES
                                + rowt*SM_STRIDE + c16*16);
        cp_async16(dst, src);
    };

    // prologue: prefetch 5 chunks
    issue_chunk(0); cp_commit();
    issue_chunk(1); cp_commit();
    issue_chunk(2); cp_commit();
    issue_chunk(3); cp_commit();
    issue_chunk(4); cp_commit();

    const int wq = (wid & 7) * 16;      // warp's 16-query slab
    const int wn = (wid >> 3) * 32;     // warp's 32-memory-col slab

    // owner-thread running top-5 (threads < 128; thread r owns query row r)
    float s0=-2.f,s1=-2.f,s2=-2.f,s3=-2.f,s4=-2.f;
    int   i0=0,i1=0,i2=0,i3=0,i4=0;

    for (int mt=0; mt<MT_PER; mt++){
        float acc[4][4];
        #pragma unroll
        for (int b=0;b<4;b++)
            #pragma unroll
            for (int d=0;d<4;d++) acc[b][d]=0.f;

        #pragma unroll 1
        for (int kc=0; kc<NKC; kc++){
            const int cidx = mt*NKC + kc;
            cp_wait<4>();               // chunk cidx resident (<=4 groups pending)
            __syncthreads();            // all warps done reading chunk cidx-1's stage
            if (cidx + 5 < NCHUNKS){ issue_chunk(cidx + 5); }
            cp_commit();

            const uint8_t* mb = (const uint8_t*)(sm + SM_OFF
                                + (cidx % NSTAGE)*CHUNK_BYTES);

            #pragma unroll
            for (int k32=0; k32<KC/32; k32++){
                uint32_t bfr[4][2];
                #pragma unroll
                for (int ntp=0; ntp<2; ntp++){
                    int brow = wn + ntp*16 + ((lane>>4)&1)*8 + (lane&7);
                    int bkB  = k32*32 + ((lane>>3)&1)*16;
                    uint32_t ba = smem_u32(mb + brow*SM_STRIDE + bkB);
                    asm volatile("ldmatrix.sync.aligned.m8n8.x4.shared.b16 {%0,%1,%2,%3}, [%4];"
                                 : "=r"(bfr[ntp*2][0]),   "=r"(bfr[ntp*2][1]),
                                   "=r"(bfr[ntp*2+1][0]), "=r"(bfr[ntp*2+1][1]) : "r"(ba));
                }
                uint32_t a0,a1,a2,a3;
                {
                    int arow = wq + (lane & 15);
                    int akB  = kc*KC + k32*32 + (lane >> 4)*16;
                    uint32_t aa = smem_u32(sQ + arow*SQ_STRIDE + akB);
                    asm volatile("ldmatrix.sync.aligned.m8n8.x4.shared.b16 {%0,%1,%2,%3}, [%4];"
                                 : "=r"(a0),"=r"(a1),"=r"(a2),"=r"(a3) : "r"(aa));
                }
                #pragma unroll
                for (int nt=0; nt<4; nt++){
                    asm volatile(
                      "mma.sync.aligned.m16n8k32.row.col.f32.e4m3.e4m3.f32 "
                      "{%0,%1,%2,%3}, {%4,%5,%6,%7}, {%8,%9}, {%0,%1,%2,%3};"
                      : "+f"(acc[nt][0]),"+f"(acc[nt][1]),
                        "+f"(acc[nt][2]),"+f"(acc[nt][3])
                      : "r"(a0),"r"(a1),"r"(a2),"r"(a3),
                        "r"(bfr[nt][0]),"r"(bfr[nt][1]));
                }
            }
        }

        const int mrow0 = mbase + mt*NT;
        bool dospill;

        if (mt == 0){
            dospill = true;
        } else {
            // ---- threshold filter: push record-beating values to buckets ----
            #pragma unroll
            for (int rp=0; rp<2; rp++){
                int r = wq + (lane>>2) + rp*8;
                float th = sThresh[r];
                #pragma unroll
                for (int nt=0; nt<4; nt++){
                    float v0 = acc[nt][rp*2+0];
                    float v1 = acc[nt][rp*2+1];
                    int c = wn + nt*8 + (lane&3)*2;
                    if (v0 > th){
                        int s = atomicAdd(&sCnt[r], 1);
                        if (s < CAP){ sBS[r*CAP+s]=v0; sBC[r*CAP+s]=c; }
                        else sOver[0] = 1;
                    }
                    if (v1 > th){
                        int s = atomicAdd(&sCnt[r], 1);
                        if (s < CAP){ sBS[r*CAP+s]=v1; sBC[r*CAP+s]=c+1; }
                        else sOver[0] = 1;
                    }
                }
            }
            __syncthreads();
            dospill = (sOver[0] != 0);
        }

        if (dospill){
            // ---- f16 spill (rare: tile 0 + overflow tiles; selection only —
            //      emitted candidates are prefiltered + exactly rescored) ----
            #pragma unroll
            for (int nt=0; nt<4; nt++){
                int r = wq + (lane >> 2);
                int c = wn + nt*8  + (lane & 3)*2;
                __half2 p0 = __floats2half2_rn(acc[nt][0], acc[nt][1]);
                __half2 p1 = __floats2half2_rn(acc[nt][2], acc[nt][3]);
                *(uint32_t*)(sSim + r*SS_STRIDEH + c)     = *(uint32_t*)&p0;
                *(uint32_t*)(sSim + (r+8)*SS_STRIDEH + c) = *(uint32_t*)&p1;
            }
            __syncthreads();
        }

        if (tid < QT){
            const int r = tid;
            const int n = (mt == 0) ? (CAP+1) : sCnt[r];
            if (n > CAP){
                // fallback: full-row scan from f16 spill
                const uint32_t* row = (const uint32_t*)(sSim + r*SS_STRIDEH);
                #pragma unroll 4
                for (int j=0; j<NT/2; j++){
                    float2 vf = __half22float2(*(__half2*)&row[j]);
                    TOP5_INSERT(vf.x, mrow0 + 2*j);
                    TOP5_INSERT(vf.y, mrow0 + 2*j + 1);
                }
            } else {
                for (int s=0; s<n; s++){
                    float v = sBS[r*CAP+s];
                    TOP5_INSERT(v, mrow0 + sBC[r*CAP+s]);
                }
            }
            sThresh[r] = s4;
            sCnt[r] = 0;
        }
        if (dospill && tid == 0) sOver[0] = 0;
        // next tile's mainloop __syncthreads orders these writes vs. reuse
    }

    if (tid < QT){
        int q = qbase + tid;
        float* cs = g_cscore + (size_t)q*NCAND + chunk*TOPK;
        int*   ci = g_cidx   + (size_t)q*NCAND + chunk*TOPK;
        cs[0]=s0; cs[1]=s1; cs[2]=s2; cs[3]=s3; cs[4]=s4;
        ci[0]=i0; ci[1]=i1; ci[2]=i2; ci[3]=i3; ci[4]=i4;
    }
}

// ---------------------------------------------------------------------------
// Kernel 4 (prefilter + exact rescore): 1 warp/query.
//   1. load 80 approx (score,pos); warp-argmax-select top-RT (16) positions
//   2. exact fp32 rescore of the 16 (4-way ILP dots)
//   3. top-5 + softmax (replicated per-lane), 5-row gather, residual add
// ---------------------------------------------------------------------------
__global__ void __launch_bounds__(256,4) merge_kernel(const float* __restrict__ x,
                             const float* __restrict__ mem,
                             float* __restrict__ out){
    __shared__ int sSel[8][RT];

    const int tid   = threadIdx.x;
    const int lane  = tid & 31;
    const int wslot = tid >> 5;
    const int q     = blockIdx.x*8 + wslot;

    // ---- load x row, inv norm ----
    const float4* xr = (const float4*)(x + (size_t)q*CDIM);
    float4 xv[4];
    float ss = 0.f;
    #pragma unroll
    for (int p=0; p<4; p++){
        xv[p] = xr[lane + p*32];
        ss += xv[p].x*xv[p].x + xv[p].y*xv[p].y + xv[p].z*xv[p].z + xv[p].w*xv[p].w;
    }
    ss = warp_sum(ss);
    float qinv = 1.0f / fmaxf(sqrtf(ss), 1e-12f);

    // ---- stage approx scores: lane holds entries lane, lane+32, lane+64 ----
    const float* csg = g_cscore + (size_t)q*NCAND;
    float c0 = csg[lane];
    float c1 = csg[lane+32];
    float c2 = (lane < NCAND-64) ? csg[lane+64] : -3.f;
    int   p0 = lane, p1 = lane+32, p2 = lane+64;

    // ---- select top-RT by approx score (ties -> lower position) ----
    #pragma unroll 1
    for (int t=0; t<RT; t++){
        float lv = c0; int lp = p0;
        if (c1 > lv || (c1 == lv && p1 < lp)){ lv = c1; lp = p1; }
        if (c2 > lv || (c2 == lv && p2 < lp)){ lv = c2; lp = p2; }
        #pragma unroll
        for (int o=16; o; o>>=1){
            float ov = __shfl_xor_sync(0xffffffffu, lv, o);
            int   op = __shfl_xor_sync(0xffffffffu, lp, o);
            if (ov > lv || (ov == lv && op < lp)){ lv = ov; lp = op; }
        }
        if (p0 == lp) c0 = -3.f;
        else if (p1 == lp) c1 = -3.f;
        else if (p2 == lp) c2 = -3.f;
        if (lane == 0) sSel[wslot][t] = lp;
    }
    __syncwarp();

    // ---- exact fp32 rescore of RT candidates, 4-way ILP ----
    const int* cig = g_cidx + (size_t)q*NCAND;
    float s0=-2.f,s1=-2.f,s2=-2.f,s3=-2.f,s4=-2.f;
    int   i0=0,i1=0,i2=0,i3=0,i4=0;

    #pragma unroll 1
    for (int jb=0; jb<RT; jb+=4){
        int   id[4];
        float d[4] = {0.f,0.f,0.f,0.f};
        #pragma unroll
        for (int u=0; u<4; u++) id[u] = cig[sSel[wslot][jb+u]];
        #pragma unroll
        for (int u=0; u<4; u++){
            const float4* mr = (const float4*)(mem + (size_t)id[u]*CDIM);
            #pragma unroll
            for (int p=0; p<4; p++){
                float4 mv = mr[lane + p*32];
                d[u] += xv[p].x*mv.x + xv[p].y*mv.y + xv[p].z*mv.z + xv[p].w*mv.w;
            }
        }
        #pragma unroll
        for (int u=0; u<4; u++) d[u] = warp_sum(d[u]);
        #pragma unroll
        for (int u=0; u<4; u++){
            float sc = d[u] * qinv * g_minv[id[u]];
            TOP5_INSERT(sc, id[u]);
        }
    }

    // ---- softmax (replicated across lanes; identical values) ----
    float e1=__expf(s1-s0), e2=__expf(s2-s0), e3=__expf(s3-s0), e4=__expf(s4-s0);
    float isum = 0.5f / (1.0f+e1+e2+e3+e4);
    float wt[TOPK] = {isum, e1*isum, e2*isum, e3*isum, e4*isum};
    int   ti[TOPK] = {i0, i1, i2, i3, i4};

    // ---- gather + residual add ----
    float4 o[4];
    #pragma unroll
    for (int p=0; p<4; p++) o[p] = xv[p];
    #pragma unroll
    for (int r=0; r<TOPK; r++){
        const float4* mr = (const float4*)(mem + (size_t)ti[r]*CDIM);
        #pragma unroll
        for (int p=0; p<4; p++){
            float4 mv = mr[lane + p*32];
            o[p].x += wt[r]*mv.x; o[p].y += wt[r]*mv.y;
            o[p].z += wt[r]*mv.z; o[p].w += wt[r]*mv.w;
        }
    }
    float4* orow = (float4*)(out + (size_t)q*CDIM);
    #pragma unroll
    for (int p=0; p<4; p++) orow[lane + p*32] = o[p];
}

// ---------------------------------------------------------------------------
extern "C" void kernel_launch(void* const* d_in, const int* in_sizes, int n_in,
                              void* d_out, int out_size){
    const float* x   = (const float*)d_in[0];   // [4,2048,512]
    const float* mem = (const float*)d_in[1];   // [32768,512]
    float* out = (float*)d_out;

    cudaFuncSetAttribute(sim_topk_fp8,
                         cudaFuncAttributeMaxDynamicSharedMemorySize, SMEM_BYTES);

    normalize_all<<<(NQ+MROWS)/8, 256>>>(x, mem);
    sim_topk_fp8<<<dim3(NCH, NQ/QT), THREADS, SMEM_BYTES>>>();
    merge_kernel<<<NQ/8, 256>>>(x, mem, out);
}

// round 17
// speedup vs baseline: 1.0574x; 1.0574x over previous
#include <cuda_runtime.h>
#include <cuda_fp16.h>
#include <cstdint>

// Problem constants
#define NQ      8192
#define CDIM    512
#define MROWS   32768
#define TOPK    5
#define NCH     16
#define MCHUNK  (MROWS/NCH)   // 2048
#define NCAND   (NCH*TOPK)    // 80
#define RT      12            // candidates exactly rescored per query

// GEMM tiling (R15 config — measured optimum of the legacy mma path)
#define THREADS   1024
#define QT        128         // queries per block
#define NT        128         // memory rows per tile
#define MT_PER    (MCHUNK/NT) // 16 tiles per block
#define KC        128         // k elements (fp8) per staged chunk
#define NKC       (CDIM/KC)   // 4
#define NCHUNKS   (MT_PER*NKC)// 64
#define NSTAGE    4           // power-of-2 ring (masked indexing)
#define CAP       12          // per-row bucket capacity per tile

#define SQ_STRIDE 528                          // bytes per sQ row (512 + 16 pad)
#define SM_STRIDE 144                          // bytes per sM row (128 + 16 pad)
#define SS_STRIDEF 130                         // floats per sSim row (128 + 2)

#define SQ_BYTES    (QT*SQ_STRIDE)             // 67584
#define CHUNK_BYTES (NT*SM_STRIDE)             // 18432
#define SM_OFF      SQ_BYTES
#define SS_OFF      (SM_OFF + NSTAGE*CHUNK_BYTES)   // 141312
#define TH_OFF      (SS_OFF + QT*SS_STRIDEF*4)      // 207872
#define CNT_OFF     (TH_OFF + 512)                  // 208384
#define BS_OFF      (CNT_OFF + 512)                 // 208896
#define BC_OFF      (BS_OFF + QT*CAP*4)             // 215040
#define OVR_OFF     (BC_OFF + QT*CAP*4)             // 221184
#define SMEM_BYTES  (OVR_OFF + 16)                  // 221200

// Scratch (device globals: allocation-free)
__device__ __align__(256) uint8_t g_qn8[(size_t)NQ*CDIM];     // e4m3 normalized queries
__device__ __align__(256) uint8_t g_mn8[(size_t)MROWS*CDIM];  // e4m3 normalized memory
__device__ float g_minv[MROWS];
__device__ float g_cscore[(size_t)NQ*NCAND];                  // fp8-approx scores
__device__ int   g_cidx[(size_t)NQ*NCAND];

__device__ __forceinline__ uint32_t smem_u32(const void* p){
    return (uint32_t)__cvta_generic_to_shared(p);
}
__device__ __forceinline__ float warp_sum(float v){
    #pragma unroll
    for (int o=16;o;o>>=1) v += __shfl_xor_sync(0xffffffffu, v, o);
    return v;
}
__device__ __forceinline__ void cp_async16(uint32_t dst, const void* src){
    asm volatile("cp.async.cg.shared.global [%0], [%1], 16;"
                 :: "r"(dst), "l"(src) : "memory");
}
__device__ __forceinline__ void cp_commit(){
    asm volatile("cp.async.commit_group;" ::: "memory");
}
template<int N>
__device__ __forceinline__ void cp_wait(){
    asm volatile("cp.async.wait_group %0;" :: "n"(N) : "memory");
}
// pack 2 floats -> e4m3x2 (a -> upper byte, b -> lower byte)
__device__ __forceinline__ uint16_t f2_e4m3x2(float a, float b){
    uint16_t r;
    asm("cvt.rn.satfinite.e4m3x2.f32 %0, %1, %2;" : "=h"(r) : "f"(a), "f"(b));
    return r;
}

// top-5 insert (strict >, earlier insertion wins ties)
#define TOP5_INSERT(v, id) do { \
    if ((v) > s4){ \
        if ((v) > s2){ \
            if ((v) > s1){ \
                if ((v) > s0){ s4=s3;i4=i3; s3=s2;i3=i2; s2=s1;i2=i1; s1=s0;i1=i0; s0=(v);i0=(id); } \
                else         { s4=s3;i4=i3; s3=s2;i3=i2; s2=s1;i2=i1; s1=(v);i1=(id); } \
            } else           { s4=s3;i4=i3; s3=s2;i3=i2; s2=(v);i2=(id); } \
        } else { \
            if ((v) > s3)    { s4=s3;i4=i3; s3=(v);i3=(id); } \
            else             { s4=(v);i4=(id); } \
        } \
    } \
} while(0)

// ---------------------------------------------------------------------------
// Kernel 1 (fused): L2-normalize all rows (fp32 in -> e4m3 out).
// Rows [0, NQ) are queries; rows [NQ, NQ+MROWS) are memory rows.
// ---------------------------------------------------------------------------
__global__ void normalize_all(const float* __restrict__ xg,
                              const float* __restrict__ mg){
    int row  = blockIdx.x*8 + (threadIdx.x >> 5);
    int lane = threadIdx.x & 31;
    const bool ismem = (row >= NQ);
    const int r = ismem ? (row - NQ) : row;
    if (ismem && r >= MROWS) return;
    const float* in = ismem ? mg : xg;
    uint8_t* outb = ismem ? g_mn8 : g_qn8;

    const float4* src = (const float4*)(in + (size_t)r*CDIM);
    float4 v[4];
    float ss = 0.f;
    #pragma unroll
    for (int w=0; w<4; w++){
        v[w] = src[lane + w*32];
        ss += v[w].x*v[w].x + v[w].y*v[w].y + v[w].z*v[w].z + v[w].w*v[w].w;
    }
    ss = warp_sum(ss);
    float inv = 1.0f / fmaxf(sqrtf(ss), 1e-12f);
    uint8_t* dst = outb + (size_t)r*CDIM;
    #pragma unroll
    for (int w=0; w<4; w++){
        uint32_t lo = f2_e4m3x2(v[w].y*inv, v[w].x*inv);   // bytes [x,y]
        uint32_t hi = f2_e4m3x2(v[w].w*inv, v[w].z*inv);   // bytes [z,w]
        *(uint32_t*)(dst + (lane + w*32)*4) = lo | (hi << 16);
    }
    if (ismem && lane==0) g_minv[r] = inv;
}

// ---------------------------------------------------------------------------
// Kernel 3: e4m3 mma.sync GEMM (R15 config; 4-stage masked cp.async ring).
// 1024 threads, 32 warps, warp tile 16q x 32n. Threshold-filtered top-5.
// Emits per-chunk top-5 indices AND fp8-approx scores.
// grid = (NCH=16, NQ/128=64) = 1024 blocks.
// ---------------------------------------------------------------------------
__global__ void __launch_bounds__(THREADS,1) sim_topk_fp8(){
    extern __shared__ __align__(16) char sm[];
    uint8_t* sQ      = (uint8_t*)sm;
    float*   sSim    = (float*)(sm + SS_OFF);
    float*   sThresh = (float*)(sm + TH_OFF);
    int*     sCnt    = (int*)(sm + CNT_OFF);
    float*   sBS     = (float*)(sm + BS_OFF);
    int*     sBC     = (int*)(sm + BC_OFF);
    int*     sOver   = (int*)(sm + OVR_OFF);

    const int tid  = threadIdx.x;
    const int lane = tid & 31;
    const int wid  = tid >> 5;
    const int chunk = blockIdx.x;
    const int qbase = blockIdx.y * QT;
    const int mbase = chunk * MCHUNK;

    if (tid == 0) sOver[0] = 0;

    // ---- Load resident Q tile (128 x 512 fp8, padded rows) ----
    {
        const uint4* gq = (const uint4*)g_qn8;   // 32 uint4 per row
        #pragma unroll
        for (int i=0; i<(QT*32)/THREADS; i++){
            int idx = tid + i*THREADS;
            int r = idx >> 5, c = idx & 31;
            uint4 v = gq[(size_t)(qbase + r)*32 + c];
            *(uint4*)(sQ + r*SQ_STRIDE + c*16) = v;
        }
    }

    // ---- producer: each thread copies 1x16B per 128x128 fp8 chunk ----
    const int rowt = tid >> 3;          // 0..127
    const int c16  = tid & 7;           // 16B column (8 per row)
    const uint8_t* gmb = g_mn8;

    auto issue_chunk = [&](int cidx){
        int mt = cidx >> 2, kc = cidx & 3;
        const uint8_t* src = gmb
            + (size_t)(mbase + mt*NT + rowt)*CDIM + kc*KC + c16*16;
        uint32_t dst = smem_u32(sm + SM_OFF + (cidx & (NSTAGE-1))*CHUNK_BYTES
                                + rowt*SM_STRIDE + c16*16);
        cp_async16(dst, src);
    };

    issue_chunk(0); cp_commit();
    issue_chunk(1); cp_commit();
    issue_chunk(2); cp_commit();

    const int wq = (wid & 7) * 16;      // warp's 16-query slab
    const int wn = (wid >> 3) * 32;     // warp's 32-memory-col slab

    // owner-thread running top-5 (threads < 128; thread r owns query row r)
    float s0=-2.f,s1=-2.f,s2=-2.f,s3=-2.f,s4=-2.f;
    int   i0=0,i1=0,i2=0,i3=0,i4=0;

    for (int mt=0; mt<MT_PER; mt++){
        float acc[4][4];
        #pragma unroll
        for (int b=0;b<4;b++)
            #pragma unroll
            for (int d=0;d<4;d++) acc[b][d]=0.f;

        #pragma unroll 1
        for (int kc=0; kc<NKC; kc++){
            const int cidx = mt*NKC + kc;
            cp_wait<2>();               // chunk cidx resident (<=2 groups pending)
            __syncthreads();            // all warps done reading chunk cidx-1's stage
            if (cidx + 3 < NCHUNKS){ issue_chunk(cidx + 3); }
            cp_commit();

            const uint8_t* mb = (const uint8_t*)(sm + SM_OFF
                                + (cidx & (NSTAGE-1))*CHUNK_BYTES);

            #pragma unroll
            for (int k32=0; k32<KC/32; k32++){
                uint32_t bfr[4][2];
                #pragma unroll
                for (int ntp=0; ntp<2; ntp++){
                    int brow = wn + ntp*16 + ((lane>>4)&1)*8 + (lane&7);
                    int bkB  = k32*32 + ((lane>>3)&1)*16;
                    uint32_t ba = smem_u32(mb + brow*SM_STRIDE + bkB);
                    asm volatile("ldmatrix.sync.aligned.m8n8.x4.shared.b16 {%0,%1,%2,%3}, [%4];"
                                 : "=r"(bfr[ntp*2][0]),   "=r"(bfr[ntp*2][1]),
                                   "=r"(bfr[ntp*2+1][0]), "=r"(bfr[ntp*2+1][1]) : "r"(ba));
                }
                uint32_t a0,a1,a2,a3;
                {
                    int arow = wq + (lane & 15);
                    int akB  = kc*KC + k32*32 + (lane >> 4)*16;
                    uint32_t aa = smem_u32(sQ + arow*SQ_STRIDE + akB);
                    asm volatile("ldmatrix.sync.aligned.m8n8.x4.shared.b16 {%0,%1,%2,%3}, [%4];"
                                 : "=r"(a0),"=r"(a1),"=r"(a2),"=r"(a3) : "r"(aa));
                }
                #pragma unroll
                for (int nt=0; nt<4; nt++){
                    asm volatile(
                      "mma.sync.aligned.m16n8k32.row.col.f32.e4m3.e4m3.f32 "
                      "{%0,%1,%2,%3}, {%4,%5,%6,%7}, {%8,%9}, {%0,%1,%2,%3};"
                      : "+f"(acc[nt][0]),"+f"(acc[nt][1]),
                        "+f"(acc[nt][2]),"+f"(acc[nt][3])
                      : "r"(a0),"r"(a1),"r"(a2),"r"(a3),
                        "r"(bfr[nt][0]),"r"(bfr[nt][1]));
                }
            }
        }

        const int mrow0 = mbase + mt*NT;
        bool dospill;

        if (mt == 0){
            dospill = true;
        } else {
            // ---- threshold filter: push record-beating values to buckets ----
            #pragma unroll
            for (int rp=0; rp<2; rp++){
                int r = wq + (lane>>2) + rp*8;
                float th = sThresh[r];
                #pragma unroll
                for (int nt=0; nt<4; nt++){
                    float v0 = acc[nt][rp*2+0];
                    float v1 = acc[nt][rp*2+1];
                    int c = wn + nt*8 + (lane&3)*2;
                    if (v0 > th){
                        int s = atomicAdd(&sCnt[r], 1);
                        if (s < CAP){ sBS[r*CAP+s]=v0; sBC[r*CAP+s]=c; }
                        else sOver[0] = 1;
                    }
                    if (v1 > th){
                        int s = atomicAdd(&sCnt[r], 1);
                        if (s < CAP){ sBS[r*CAP+s]=v1; sBC[r*CAP+s]=c+1; }
                        else sOver[0] = 1;
                    }
                }
            }
            __syncthreads();
            dospill = (sOver[0] != 0);
        }

        if (dospill){
            // ---- fp32 spill (rare: tile 0 + overflow tiles) ----
            #pragma unroll
            for (int nt=0; nt<4; nt++){
                int r = wq + (lane >> 2);
                int c = wn + nt*8  + (lane & 3)*2;
                *(float2*)(sSim + r*SS_STRIDEF + c) =
                    make_float2(acc[nt][0], acc[nt][1]);
                *(float2*)(sSim + (r+8)*SS_STRIDEF + c) =
                    make_float2(acc[nt][2], acc[nt][3]);
            }
            __syncthreads();
        }

        if (tid < QT){
            const int r = tid;
            const int n = (mt == 0) ? (CAP+1) : sCnt[r];
            if (n > CAP){
                // fallback: exact full-row scan from spill
                const float* row = sSim + r*SS_STRIDEF;
                #pragma unroll 4
                for (int c=0; c<NT; c++){
                    float v = row[c];
                    TOP5_INSERT(v, mrow0 + c);
                }
            } else {
                for (int s=0; s<n; s++){
                    float v = sBS[r*CAP+s];
                    TOP5_INSERT(v, mrow0 + sBC[r*CAP+s]);
                }
            }
            sThresh[r] = s4;
            sCnt[r] = 0;
        }
        if (dospill && tid == 0) sOver[0] = 0;
        // next tile's mainloop __syncthreads orders these writes vs. reuse
    }

    if (tid < QT){
        int q = qbase + tid;
        float* cs = g_cscore + (size_t)q*NCAND + chunk*TOPK;
        int*   ci = g_cidx   + (size_t)q*NCAND + chunk*TOPK;
        cs[0]=s0; cs[1]=s1; cs[2]=s2; cs[3]=s3; cs[4]=s4;
        ci[0]=i0; ci[1]=i1; ci[2]=i2; ci[3]=i3; ci[4]=i4;
    }
}

// ---------------------------------------------------------------------------
// Kernel 4 (prefilter + exact rescore): 1 warp/query.
//   1. load 80 approx (score,pos); warp-argmax-select top-RT (12) positions
//   2. exact fp32 rescore of the 12 (4-way ILP dots)
//   3. top-5 + softmax (replicated per-lane), 5-row gather, residual add
// ---------------------------------------------------------------------------
__global__ void __launch_bounds__(256,4) merge_kernel(const float* __restrict__ x,
                             const float* __restrict__ mem,
                             float* __restrict__ out){
    __shared__ int sSel[8][RT];

    const int tid   = threadIdx.x;
    const int lane  = tid & 31;
    const int wslot = tid >> 5;
    const int q     = blockIdx.x*8 + wslot;

    // ---- load x row, inv norm ----
    const float4* xr = (const float4*)(x + (size_t)q*CDIM);
    float4 xv[4];
    float ss = 0.f;
    #pragma unroll
    for (int p=0; p<4; p++){
        xv[p] = xr[lane + p*32];
        ss += xv[p].x*xv[p].x + xv[p].y*xv[p].y + xv[p].z*xv[p].z + xv[p].w*xv[p].w;
    }
    ss = warp_sum(ss);
    float qinv = 1.0f / fmaxf(sqrtf(ss), 1e-12f);

    // ---- stage approx scores: lane holds entries lane, lane+32, lane+64 ----
    const float* csg = g_cscore + (size_t)q*NCAND;
    float c0 = csg[lane];
    float c1 = csg[lane+32];
    float c2 = (lane < NCAND-64) ? csg[lane+64] : -3.f;
    int   p0 = lane, p1 = lane+32, p2 = lane+64;

    // ---- select top-RT by approx score (ties -> lower position) ----
    #pragma unroll 1
    for (int t=0; t<RT; t++){
        float lv = c0; int lp = p0;
        if (c1 > lv || (c1 == lv && p1 < lp)){ lv = c1; lp = p1; }
        if (c2 > lv || (c2 == lv && p2 < lp)){ lv = c2; lp = p2; }
        #pragma unroll
        for (int o=16; o; o>>=1){
            float ov = __shfl_xor_sync(0xffffffffu, lv, o);
            int   op = __shfl_xor_sync(0xffffffffu, lp, o);
            if (ov > lv || (ov == lv && op < lp)){ lv = ov; lp = op; }
        }
        if (p0 == lp) c0 = -3.f;
        else if (p1 == lp) c1 = -3.f;
        else if (p2 == lp) c2 = -3.f;
        if (lane == 0) sSel[wslot][t] = lp;
    }
    __syncwarp();

    // ---- exact fp32 rescore of RT candidates, 4-way ILP ----
    const int* cig = g_cidx + (size_t)q*NCAND;
    float s0=-2.f,s1=-2.f,s2=-2.f,s3=-2.f,s4=-2.f;
    int   i0=0,i1=0,i2=0,i3=0,i4=0;

    #pragma unroll 1
    for (int jb=0; jb<RT; jb+=4){
        int   id[4];
        float d[4] = {0.f,0.f,0.f,0.f};
        #pragma unroll
        for (int u=0; u<4; u++) id[u] = cig[sSel[wslot][jb+u]];
        #pragma unroll
        for (int u=0; u<4; u++){
            const float4* mr = (const float4*)(mem + (size_t)id[u]*CDIM);
            #pragma unroll
            for (int p=0; p<4; p++){
                float4 mv = mr[lane + p*32];
                d[u] += xv[p].x*mv.x + xv[p].y*mv.y + xv[p].z*mv.z + xv[p].w*mv.w;
            }
        }
        #pragma unroll
        for (int u=0; u<4; u++) d[u] = warp_sum(d[u]);
        #pragma unroll
        for (int u=0; u<4; u++){
            float sc = d[u] * qinv * g_minv[id[u]];
            TOP5_INSERT(sc, id[u]);
        }
    }

    // ---- softmax (replicated across lanes; identical values) ----
    float e1=__expf(s1-s0), e2=__expf(s2-s0), e3=__expf(s3-s0), e4=__expf(s4-s0);
    float isum = 0.5f / (1.0f+e1+e2+e3+e4);
    float wt[TOPK] = {isum, e1*isum, e2*isum, e3*isum, e4*isum};
    int   ti[TOPK] = {i0, i1, i2, i3, i4};

    // ---- gather + residual add ----
    float4 o[4];
    #pragma unroll
    for (int p=0; p<4; p++) o[p] = xv[p];
    #pragma unroll
    for (int r=0; r<TOPK; r++){
        const float4* mr = (const float4*)(mem + (size_t)ti[r]*CDIM);
        #pragma unroll
        for (int p=0; p<4; p++){
            float4 mv = mr[lane + p*32];
            o[p].x += wt[r]*mv.x; o[p].y += wt[r]*mv.y;
            o[p].z += wt[r]*mv.z; o[p].w += wt[r]*mv.w;
        }
    }
    float4* orow = (float4*)(out + (size_t)q*CDIM);
    #pragma unroll
    for (int p=0; p<4; p++) orow[lane + p*32] = o[p];
}

// ---------------------------------------------------------------------------
extern "C" void kernel_launch(void* const* d_in, const int* in_sizes, int n_in,
                              void* d_out, int out_size){
    const float* x   = (const float*)d_in[0];   // [4,2048,512]
    const float* mem = (const float*)d_in[1];   // [32768,512]
    float* out = (float*)d_out;

    cudaFuncSetAttribute(sim_topk_fp8,
                         cudaFuncAttributeMaxDynamicSharedMemorySize, SMEM_BYTES);

    normalize_all<<<(NQ+MROWS)/8, 256>>>(x, mem);
    sim_topk_fp8<<<dim3(NCH, NQ/QT), THREADS, SMEM_BYTES>>>();
    merge_kernel<<<NQ/8, 256>>>(x, mem, out);
}